// round 8
// baseline (speedup 1.0000x reference)
#include <cuda_runtime.h>
#include <math.h>
#include <float.h>

#define NUM_CLASSES 200
#define NUM_PROTO   10
#define EMBED_D     512
#define NQ          8192
#define NBC         (NQ / 128)    // 64 big-chunks of 128 labels
#define ITERS       5
#define EPSF        0.01f
#define INV_EPS     100.0f
#define EPS_LOG     1e-8f
#define NCAP        192           // per-class row capacity (mean n_c ~41, sd 6.4)
#define PARTS       3             // k_dots blocks per class
#define FULLM       0xffffffffu

// ---------------- scratch (allocation-free: __device__ globals) ----------------
__device__ int   g_lab[NQ];                       // labels as int32
__device__ int   g_cnt[NUM_CLASSES];
__device__ int   g_ltc[NUM_CLASSES];              // #(labels < c) (fallback offset)
__device__ int   g_idx[NUM_CLASSES * NCAP];
__device__ float g_S [NUM_CLASSES * NCAP * NUM_PROTO];
__device__ float g_iv[NUM_CLASSES * NCAP];
// fallback scratch (only if a class exceeds NCAP rows; statistically unreachable)
__device__ int   g_fidx[NQ];
__device__ float g_Sf[NQ * NUM_PROTO];
__device__ float g_if[NQ];
__device__ float g_vf[NQ];

// ---------------- K1: detect label dtype, convert to int32 --------------------
__global__ void k_lab(const void* __restrict__ labels_raw) {
    __shared__ int s_is64;
    int tid = threadIdx.x;
    if (tid < 32) {
        long long v = ((const long long*)labels_raw)[tid];
        unsigned bal = __ballot_sync(FULLM, v >= 0 && v < NUM_CLASSES);
        if (tid == 0) s_is64 = (__popc(bal) >= 16) ? 1 : 0;
    }
    __syncthreads();
    int i = blockIdx.x * blockDim.x + tid;
    g_lab[i] = s_is64 ? (int)((const long long*)labels_raw)[i]
                      : ((const int*)labels_raw)[i];
}

__device__ __forceinline__ float dot4(float4 a, float4 b) {
    return a.x * b.x + a.y * b.y + a.z * b.z + a.w * b.w;
}
__device__ __forceinline__ float warp_sum(float v) {
    #pragma unroll
    for (int o = 16; o; o >>= 1) v += __shfl_xor_sync(FULLM, v, o);
    return v;
}
__device__ __forceinline__ float warp_max(float v) {
    #pragma unroll
    for (int o = 16; o; o >>= 1) v = fmaxf(v, __shfl_xor_sync(FULLM, v, o));
    return v;
}

// ---------------- K2: per-class index lists (ballot-rank scan) -----------------
__global__ void __launch_bounds__(256) k_idx() {
    __shared__ int ccnt[NBC];
    __shared__ int s_n, s_lt;
    int c = blockIdx.x, tid = threadIdx.x;
    int wid = tid >> 5, lane = tid & 31;
    if (tid == 0) s_lt = 0;
    __syncthreads();

    const int4* lab4 = (const int4*)g_lab;
    int lt_local = 0;
    #pragma unroll
    for (int k = 0; k < NBC / 8; k++) {           // 8 big-chunks per warp
        int bc = wid * (NBC / 8) + k;
        int4 v = lab4[bc * 32 + lane];
        unsigned b0 = __ballot_sync(FULLM, v.x == c);
        unsigned b1 = __ballot_sync(FULLM, v.y == c);
        unsigned b2 = __ballot_sync(FULLM, v.z == c);
        unsigned b3 = __ballot_sync(FULLM, v.w == c);
        unsigned l0 = __ballot_sync(FULLM, v.x < c);
        unsigned l1 = __ballot_sync(FULLM, v.y < c);
        unsigned l2 = __ballot_sync(FULLM, v.z < c);
        unsigned l3 = __ballot_sync(FULLM, v.w < c);
        if (lane == 0) {
            ccnt[bc] = __popc(b0) + __popc(b1) + __popc(b2) + __popc(b3);
            lt_local += __popc(l0) + __popc(l1) + __popc(l2) + __popc(l3);
        }
    }
    if (lane == 0 && lt_local) atomicAdd(&s_lt, lt_local);   // int: deterministic
    __syncthreads();

    if (wid == 0) {                                // exclusive scan over 64 counts
        int base = 0;
        #pragma unroll
        for (int g = 0; g < NBC / 32; g++) {
            int v = ccnt[g * 32 + lane];
            int inc = v;
            #pragma unroll
            for (int o = 1; o < 32; o <<= 1) {
                int t = __shfl_up_sync(FULLM, inc, o);
                if (lane >= o) inc += t;
            }
            ccnt[g * 32 + lane] = base + inc - v;
            base += __shfl_sync(FULLM, inc, 31);
        }
        if (lane == 0) s_n = base;
    }
    __syncthreads();

    int n_c = s_n, lt = s_lt;
    if (tid == 0) { g_cnt[c] = n_c; g_ltc[c] = lt; }
    if (n_c == 0) return;
    bool sm = (n_c <= NCAP);
    int* dst = sm ? (g_idx + c * NCAP) : (g_fidx + lt);

    #pragma unroll
    for (int k = 0; k < NBC / 8; k++) {
        int bc = wid * (NBC / 8) + k;
        int4 v = lab4[bc * 32 + lane];
        int n0 = bc * 128 + lane * 4;
        unsigned b0 = __ballot_sync(FULLM, v.x == c);
        unsigned b1 = __ballot_sync(FULLM, v.y == c);
        unsigned b2 = __ballot_sync(FULLM, v.z == c);
        unsigned b3 = __ballot_sync(FULLM, v.w == c);
        unsigned ltm = (1u << lane) - 1u;
        int base = ccnt[bc];
        int c0 = __popc(b0), c1 = __popc(b1), c2 = __popc(b2);
        if (v.x == c) dst[base + __popc(b0 & ltm)] = n0;
        if (v.y == c) dst[base + c0 + __popc(b1 & ltm)] = n0 + 1;
        if (v.z == c) dst[base + c0 + c1 + __popc(b2 & ltm)] = n0 + 2;
        if (v.w == c) dst[base + c0 + c1 + c2 + __popc(b3 & ltm)] = n0 + 3;
    }
}

// ---------------- K3: DRAM-heavy dots, 3 blocks per class ----------------------
__global__ void __launch_bounds__(256) k_dots(const float* __restrict__ tokens,
                                              const float* __restrict__ protos) {
    __shared__ __align__(16) float sp[NUM_PROTO * EMBED_D];   // 20 KB
    int c = blockIdx.x, p = blockIdx.y;
    int n_c = g_cnt[c];
    if (n_c == 0) return;
    int tid = threadIdx.x, wid = tid >> 5, lane = tid & 31;

    {
        const float4* pg = (const float4*)(protos + (size_t)c * NUM_PROTO * EMBED_D);
        float4* ps = (float4*)sp;
        for (int i = tid; i < NUM_PROTO * EMBED_D / 4; i += 256) ps[i] = pg[i];
    }
    __syncthreads();

    bool sm = (n_c <= NCAP);
    int lt = g_ltc[c];
    const int* IDX = sm ? (g_idx + c * NCAP) : (g_fidx + lt);
    float* S  = sm ? (g_S + (size_t)c * NCAP * NUM_PROTO) : (g_Sf + (size_t)lt * NUM_PROTO);
    float* IV = sm ? (g_iv + c * NCAP) : (g_if + lt);

    // part p handles rows i = p + PARTS*(wid + 8k): balanced across 3 blocks
    for (int i = p + PARTS * wid; i < n_c; i += PARTS * 8) {
        int n = IDX[i];
        const float4* tp = (const float4*)(tokens + (size_t)n * EMBED_D);
        float4 t0 = tp[lane], t1 = tp[lane + 32], t2 = tp[lane + 64], t3 = tp[lane + 96];
        float ss = dot4(t0, t0) + dot4(t1, t1) + dot4(t2, t2) + dot4(t3, t3);
        ss = warp_sum(ss);
        float inv = rsqrtf(ss);
        if (lane == 0) IV[i] = inv;
        #pragma unroll
        for (int j = 0; j < NUM_PROTO; j++) {
            const float4* pp = (const float4*)(sp + j * EMBED_D);
            float d = dot4(t0, pp[lane]) + dot4(t1, pp[lane + 32]) +
                      dot4(t2, pp[lane + 64]) + dot4(t3, pp[lane + 96]);
            d = warp_sum(d);
            if (lane == 0) S[i * NUM_PROTO + j] = d * inv;
        }
    }
}

// ---------------- K4 body: Sinkhorn + accumulate + blend + norm ----------------
template<bool SM>
__device__ __forceinline__ void fin_body(
    int c, int n_c,
    const float* __restrict__ tokens, const float* __restrict__ protos,
    float* __restrict__ out,
    const int* IDX, float* S, float* V, float* IV,
    float* su, float* red, float* sinv)
{
    int tid = threadIdx.x;
    int wid = tid >> 5, lane = tid & 31;

    for (int i = tid; i < n_c; i += 512) V[i] = 0.0f;
    __syncthreads();

    const float log_a = __logf(1.0f / (float)NUM_PROTO + EPS_LOG);
    const float log_b = __logf(1.0f / (float)n_c + EPS_LOG);
    for (int it = 0; it < ITERS; it++) {
        if (wid < NUM_PROTO) {         // u: warp j, two-pass max -> sum LSE
            int j = wid;
            float m = -FLT_MAX;
            for (int i = lane; i < n_c; i += 32)
                m = fmaxf(m, S[i * NUM_PROTO + j] + V[i]);
            m = warp_max(m);
            float s = 0.0f;
            for (int i = lane; i < n_c; i += 32)
                s += __expf((S[i * NUM_PROTO + j] + V[i] - m) * INV_EPS);
            s = warp_sum(s);
            if (lane == 0) su[j] = EPSF * log_a - m - EPSF * __logf(s);
        }
        __syncthreads();
        for (int i = tid; i < n_c; i += 512) {   // v: thread per row
            float b[NUM_PROTO];
            float m = -FLT_MAX;
            #pragma unroll
            for (int j = 0; j < NUM_PROTO; j++) {
                b[j] = S[i * NUM_PROTO + j] + su[j];
                m = fmaxf(m, b[j]);
            }
            float s = 0.0f;
            #pragma unroll
            for (int j = 0; j < NUM_PROTO; j++) s += __expf((b[j] - m) * INV_EPS);
            V[i] = EPSF * log_b - m - EPSF * __logf(s);
        }
        __syncthreads();
    }

    // transport weights, column-normalized, * inv-norm, in place
    for (int i = tid; i < n_c; i += 512) {
        float vv = V[i];
        float w[NUM_PROTO];
        float cs = 0.0f;
        #pragma unroll
        for (int j = 0; j < NUM_PROTO; j++) {
            w[j] = __expf((S[i * NUM_PROTO + j] + su[j] + vv) * INV_EPS);
            cs += w[j];
        }
        float sc = IV[i] / cs;
        #pragma unroll
        for (int j = 0; j < NUM_PROTO; j++) S[i * NUM_PROTO + j] = w[j] * sc;
    }
    __syncthreads();

    // accumulation: thread owns dim d; tokens come from L2 (read once in k_dots)
    int d = tid;
    float acc[NUM_PROTO];
    #pragma unroll
    for (int j = 0; j < NUM_PROTO; j++) acc[j] = 0.0f;
    int i = 0;
    for (; i + 2 <= n_c; i += 2) {
        float ta = __ldg(tokens + (size_t)IDX[i]     * EMBED_D + d);
        float tb = __ldg(tokens + (size_t)IDX[i + 1] * EMBED_D + d);
        const float2* ra = (const float2*)(S + i * NUM_PROTO);        // 8B-aligned
        const float2* rb = (const float2*)(S + (i + 1) * NUM_PROTO);
        #pragma unroll
        for (int h = 0; h < 5; h++) {
            float2 wa = ra[h], wb = rb[h];
            acc[2*h]   += wa.x * ta + wb.x * tb;
            acc[2*h+1] += wa.y * ta + wb.y * tb;
        }
    }
    if (i < n_c) {
        float ta = __ldg(tokens + (size_t)IDX[i] * EMBED_D + d);
        const float2* ra = (const float2*)(S + i * NUM_PROTO);
        #pragma unroll
        for (int h = 0; h < 5; h++) {
            float2 wa = ra[h];
            acc[2*h] += wa.x * ta; acc[2*h+1] += wa.y * ta;
        }
    }

    // momentum blend (protos from L2) + batched per-row l2norm + writeout
    float r[NUM_PROTO];
    #pragma unroll
    for (int j = 0; j < NUM_PROTO; j++) {
        r[j] = 0.98f * __ldg(protos + (size_t)(c * NUM_PROTO + j) * EMBED_D + d)
             + 0.02f * acc[j];
        float x = warp_sum(r[j] * r[j]);
        if (lane == 0) red[wid * NUM_PROTO + j] = x;
    }
    __syncthreads();
    if (wid < NUM_PROTO) {
        int j = wid;
        float y = (lane < 16) ? red[lane * NUM_PROTO + j] : 0.0f;
        y = warp_sum(y);
        if (lane == 0) sinv[j] = rsqrtf(y);
    }
    __syncthreads();
    #pragma unroll
    for (int j = 0; j < NUM_PROTO; j++)
        out[(size_t)(c * NUM_PROTO + j) * EMBED_D + d] = r[j] * sinv[j];
}

// ---------------- K4: Sinkhorn + finish ----------------------------------------
__global__ void __launch_bounds__(512) k_fin(const float* __restrict__ tokens,
                                             const float* __restrict__ protos,
                                             float* __restrict__ out) {
    __shared__ __align__(8) float sS[NCAP * NUM_PROTO];   // 7.5 KB
    __shared__ float sV[NCAP];
    __shared__ float sIv[NCAP];
    __shared__ int   sidx[NCAP];
    __shared__ float su[NUM_PROTO];
    __shared__ float red[16 * NUM_PROTO];
    __shared__ float sinv[NUM_PROTO];

    int c = blockIdx.x, tid = threadIdx.x;
    int n_c = g_cnt[c];
    if (n_c == 0) {      // out = l2norm(0.98*proto) = proto (unit-norm input)
        #pragma unroll
        for (int j = 0; j < NUM_PROTO; j++) {
            size_t r = (size_t)(c * NUM_PROTO + j) * EMBED_D + tid;
            out[r] = protos[r];
        }
        return;
    }
    if (n_c <= NCAP) {
        const float* gs = g_S + (size_t)c * NCAP * NUM_PROTO;
        for (int i = tid; i < n_c * NUM_PROTO; i += 512) sS[i] = gs[i];
        for (int i = tid; i < n_c; i += 512) {
            sIv[i]  = g_iv[c * NCAP + i];
            sidx[i] = g_idx[c * NCAP + i];
        }
        __syncthreads();
        fin_body<true >(c, n_c, tokens, protos, out, sidx, sS, sV, sIv, su, red, sinv);
    } else {             // statistically unreachable global-scratch fallback
        int lt = g_ltc[c];
        fin_body<false>(c, n_c, tokens, protos, out,
                        g_fidx + lt, g_Sf + (size_t)lt * NUM_PROTO,
                        g_vf + lt, g_if + lt, su, red, sinv);
    }
}

// -------------------------------- launch ---------------------------------------
extern "C" void kernel_launch(void* const* d_in, const int* in_sizes, int n_in,
                              void* d_out, int out_size) {
    const float* tokens = (const float*)d_in[0];
    const void*  labels = d_in[1];
    const float* protos = (const float*)d_in[2];
    float* out = (float*)d_out;

    k_lab <<<NQ / 1024, 1024>>>(labels);
    k_idx <<<NUM_CLASSES, 256>>>();
    k_dots<<<dim3(NUM_CLASSES, PARTS), 256>>>(tokens, protos);
    k_fin <<<NUM_CLASSES, 512>>>(tokens, protos, out);
}

// round 9
// speedup vs baseline: 1.1353x; 1.1353x over previous
#include <cuda_runtime.h>
#include <math.h>
#include <float.h>

#define NUM_CLASSES 200
#define NUM_PROTO   10
#define EMBED_D     512
#define NQ          8192
#define ITERS       5
#define EPSF        0.01f
#define INV_EPS     100.0f
#define EPS_LOG     1e-8f
#define NCAP        192           // per-class row capacity (mean n_c ~41, sd 6.4)
#define FULLM       0xffffffffu
#define BAR320()    asm volatile("bar.sync 1, 320;" ::: "memory")

// ---- fallback scratch (only if a class exceeds NCAP rows; statistically unreachable)
__device__ int   g_fidx[NQ];
__device__ float g_Sf[NQ * NUM_PROTO];
__device__ float g_vf[NQ];
__device__ float g_if[NQ];

__device__ __forceinline__ float dot4(float4 a, float4 b) {
    return a.x * b.x + a.y * b.y + a.z * b.z + a.w * b.w;
}
__device__ __forceinline__ float warp_sum(float v) {
    #pragma unroll
    for (int o = 16; o; o >>= 1) v += __shfl_xor_sync(FULLM, v, o);
    return v;
}
__device__ __forceinline__ float warp_max(float v) {
    #pragma unroll
    for (int o = 16; o; o >>= 1) v = fmaxf(v, __shfl_xor_sync(FULLM, v, o));
    return v;
}

// ---------------- fused per-class body ------------------------------------------
template<bool SM>
__device__ __forceinline__ void class_body(
    int c, int n_c,
    const float* __restrict__ tokens,
    float* __restrict__ out,
    const float* sp, const int* IDX,
    float* S, float* V, float* IV,
    float* su, float* red, float* sinv)
{
    int tid = threadIdx.x;
    int wid = tid >> 5, lane = tid & 31;

    for (int i = tid; i < n_c; i += 512) V[i] = 0.0f;
    __syncthreads();

    // --- phase A: per-row norm + 10 masked dots (warp per row, idx prefetched) ---
    {
        int i = wid;
        int n = (i < n_c) ? IDX[i] : 0;
        while (i < n_c) {
            int i2 = i + 16;
            int n2 = (i2 < n_c) ? IDX[i2] : 0;      // prefetch next row's index
            const float4* tp = (const float4*)(tokens + (size_t)n * EMBED_D);
            float4 t0 = tp[lane], t1 = tp[lane + 32], t2 = tp[lane + 64], t3 = tp[lane + 96];
            float ss = dot4(t0, t0) + dot4(t1, t1) + dot4(t2, t2) + dot4(t3, t3);
            ss = warp_sum(ss);
            float inv = rsqrtf(ss);
            if (lane == 0) IV[i] = inv;
            #pragma unroll
            for (int j = 0; j < NUM_PROTO; j++) {
                const float4* pp = (const float4*)(sp + j * EMBED_D);
                float d = dot4(t0, pp[lane]) + dot4(t1, pp[lane + 32]) +
                          dot4(t2, pp[lane + 64]) + dot4(t3, pp[lane + 96]);
                d = warp_sum(d);
                if (lane == 0) S[i * NUM_PROTO + j] = d * inv;
            }
            i = i2; n = n2;
        }
    }
    __syncthreads();

    // --- phase B: 5 Sinkhorn iterations on warps 0-9 only (named barrier) ---
    if (wid < NUM_PROTO) {
        const float log_a = __logf(1.0f / (float)NUM_PROTO + EPS_LOG);
        const float log_b = __logf(1.0f / (float)n_c + EPS_LOG);
        for (int it = 0; it < ITERS; it++) {
            int j = wid;                       // u: warp j, two-pass max -> sum LSE
            float m = -FLT_MAX;
            for (int i = lane; i < n_c; i += 32)
                m = fmaxf(m, S[i * NUM_PROTO + j] + V[i]);
            m = warp_max(m);
            float s = 0.0f;
            for (int i = lane; i < n_c; i += 32)
                s += __expf((S[i * NUM_PROTO + j] + V[i] - m) * INV_EPS);
            s = warp_sum(s);
            if (lane == 0) su[j] = EPSF * log_a - m - EPSF * __logf(s);
            BAR320();
            for (int i = tid; i < n_c; i += 320) {   // v: thread per row (320 thr)
                float b[NUM_PROTO];
                float mm = -FLT_MAX;
                #pragma unroll
                for (int j2 = 0; j2 < NUM_PROTO; j2++) {
                    b[j2] = S[i * NUM_PROTO + j2] + su[j2];
                    mm = fmaxf(mm, b[j2]);
                }
                float ss = 0.0f;
                #pragma unroll
                for (int j2 = 0; j2 < NUM_PROTO; j2++) ss += __expf((b[j2] - mm) * INV_EPS);
                V[i] = EPSF * log_b - mm - EPSF * __logf(ss);
            }
            BAR320();
        }
    }
    __syncthreads();   // warps 10-15 rejoin; Sinkhorn results visible

    // --- phase C: column-normalized transport weights * inv-norm, in place ---
    for (int i = tid; i < n_c; i += 512) {
        float vv = V[i];
        float w[NUM_PROTO];
        float cs = 0.0f;
        #pragma unroll
        for (int j = 0; j < NUM_PROTO; j++) {
            w[j] = __expf((S[i * NUM_PROTO + j] + su[j] + vv) * INV_EPS);
            cs += w[j];
        }
        float sc = IV[i] / cs;       // fold 1/||tok|| so phase D uses raw tokens
        #pragma unroll
        for (int j = 0; j < NUM_PROTO; j++) S[i * NUM_PROTO + j] = w[j] * sc;
    }
    __syncthreads();

    // --- phase D: new_protos = weights^T @ raw_tokens (thread owns dim d) ---
    int d = tid;
    float acc[NUM_PROTO];
    #pragma unroll
    for (int j = 0; j < NUM_PROTO; j++) acc[j] = 0.0f;
    int i = 0;
    for (; i + 4 <= n_c; i += 4) {               // 4 L1-warm loads in flight
        float t0 = __ldg(tokens + (size_t)IDX[i]     * EMBED_D + d);
        float t1 = __ldg(tokens + (size_t)IDX[i + 1] * EMBED_D + d);
        float t2 = __ldg(tokens + (size_t)IDX[i + 2] * EMBED_D + d);
        float t3 = __ldg(tokens + (size_t)IDX[i + 3] * EMBED_D + d);
        #pragma unroll
        for (int h = 0; h < 5; h++) {
            float2 w0 = *(const float2*)(S + (i)     * NUM_PROTO + 2*h);
            float2 w1 = *(const float2*)(S + (i + 1) * NUM_PROTO + 2*h);
            float2 w2 = *(const float2*)(S + (i + 2) * NUM_PROTO + 2*h);
            float2 w3 = *(const float2*)(S + (i + 3) * NUM_PROTO + 2*h);
            acc[2*h]   += w0.x * t0 + w1.x * t1 + w2.x * t2 + w3.x * t3;
            acc[2*h+1] += w0.y * t0 + w1.y * t1 + w2.y * t2 + w3.y * t3;
        }
    }
    for (; i < n_c; i++) {
        float t0 = __ldg(tokens + (size_t)IDX[i] * EMBED_D + d);
        #pragma unroll
        for (int h = 0; h < 5; h++) {
            float2 w0 = *(const float2*)(S + i * NUM_PROTO + 2*h);
            acc[2*h] += w0.x * t0; acc[2*h+1] += w0.y * t0;
        }
    }

    // --- phase E: momentum blend + batched per-row l2norm + writeout ---
    float r[NUM_PROTO];
    #pragma unroll
    for (int j = 0; j < NUM_PROTO; j++) {
        r[j] = 0.98f * sp[j * EMBED_D + d] + 0.02f * acc[j];
        float x = warp_sum(r[j] * r[j]);
        if (lane == 0) red[wid * NUM_PROTO + j] = x;
    }
    __syncthreads();
    if (wid < NUM_PROTO) {
        int j = wid;
        float y = (lane < 16) ? red[lane * NUM_PROTO + j] : 0.0f;
        y = warp_sum(y);
        if (lane == 0) sinv[j] = rsqrtf(y);
    }
    __syncthreads();
    #pragma unroll
    for (int j = 0; j < NUM_PROTO; j++)
        out[(size_t)(c * NUM_PROTO + j) * EMBED_D + d] = r[j] * sinv[j];
}

// ---------------- single fused kernel -------------------------------------------
__global__ void __launch_bounds__(512) k_main(const float* __restrict__ tokens,
                                              const void*  __restrict__ labels_raw,
                                              const float* __restrict__ protos,
                                              float* __restrict__ out) {
    __shared__ __align__(16) float sp[NUM_PROTO * EMBED_D];   // 20 KB
    __shared__ __align__(8)  float ssS[NCAP * NUM_PROTO];     // 7.5 KB
    __shared__ float    ssV[NCAP];
    __shared__ float    ssI[NCAP];
    __shared__ int      sidx[NCAP];
    __shared__ unsigned cmask[256];     // 256 sub-chunk ballot masks (32 labels each)
    __shared__ int      cpre[256];      // exclusive prefix (within 32-group)
    __shared__ int      wsum[8];        // group offsets
    __shared__ float    su[NUM_PROTO];
    __shared__ float    red[16 * NUM_PROTO];
    __shared__ float    sinv[NUM_PROTO];
    __shared__ int      s_n, s_lt;

    int c    = blockIdx.x;
    int tid  = threadIdx.x;
    int wid  = tid >> 5, lane = tid & 31;

    // stage prototypes early (DRAM loads in flight during label scan)
    {
        const float4* pg = (const float4*)(protos + (size_t)c * NUM_PROTO * EMBED_D);
        float4* ps = (float4*)sp;
        for (int i = tid; i < NUM_PROTO * EMBED_D / 4; i += 512) ps[i] = pg[i];
    }
    if (tid == 0) s_lt = 0;

    // per-warp label dtype detection (uniform branch, hoisted out of load loops)
    const long long* l64 = (const long long*)labels_raw;
    bool is64;
    {
        long long v = l64[lane];
        unsigned bal = __ballot_sync(FULLM, v >= 0 && v < NUM_CLASSES);
        is64 = (__popc(bal) >= 16);
    }
    __syncthreads();

    // --- pass 1: thread-parallel label load + ballot masks cached in smem ---
    const int4* l4 = (const int4*)labels_raw;
    int ltl = 0;
    if (!is64) {
        #pragma unroll
        for (int k = 0; k < 4; k++) {            // int4 = 4 labels; 2048 int4 total
            int4 v = l4[tid + 512 * k];
            unsigned b0 = __ballot_sync(FULLM, v.x == c);
            unsigned b1 = __ballot_sync(FULLM, v.y == c);
            unsigned b2 = __ballot_sync(FULLM, v.z == c);
            unsigned b3 = __ballot_sync(FULLM, v.w == c);
            unsigned l0 = __ballot_sync(FULLM, v.x < c);
            unsigned l1 = __ballot_sync(FULLM, v.y < c);
            unsigned l2 = __ballot_sync(FULLM, v.z < c);
            unsigned l3 = __ballot_sync(FULLM, v.w < c);
            if (lane == 0) {
                int mb = (k * 16 + wid) * 4;
                cmask[mb] = b0; cmask[mb+1] = b1; cmask[mb+2] = b2; cmask[mb+3] = b3;
                ltl += __popc(l0) + __popc(l1) + __popc(l2) + __popc(l3);
            }
        }
    } else {
        #pragma unroll
        for (int k = 0; k < 8; k++) {            // int4 = 2 int64 labels (.x, .z)
            int4 v = l4[tid + 512 * k];
            unsigned b0 = __ballot_sync(FULLM, v.x == c);
            unsigned b1 = __ballot_sync(FULLM, v.z == c);
            unsigned l0 = __ballot_sync(FULLM, v.x < c);
            unsigned l1 = __ballot_sync(FULLM, v.z < c);
            if (lane == 0) {
                int mb = (k * 16 + wid) * 2;
                cmask[mb] = b0; cmask[mb+1] = b1;
                ltl += __popc(l0) + __popc(l1);
            }
        }
    }
    if (lane == 0 && ltl) atomicAdd(&s_lt, ltl);     // int: deterministic
    __syncthreads();

    // --- two-level exclusive prefix over 256 mask popcounts ---
    if (wid < 8) {
        int v = __popc(cmask[wid * 32 + lane]);
        int inc = v;
        #pragma unroll
        for (int o = 1; o < 32; o <<= 1) {
            int t = __shfl_up_sync(FULLM, inc, o);
            if (lane >= o) inc += t;
        }
        cpre[wid * 32 + lane] = inc - v;
        if (lane == 31) wsum[wid] = inc;
    }
    __syncthreads();
    if (wid == 0 && lane < 8) {
        int v = wsum[lane];
        int inc = v;
        #pragma unroll
        for (int o = 1; o < 8; o <<= 1) {
            int t = __shfl_up_sync(0xffu, inc, o);
            if (lane >= o) inc += t;
        }
        wsum[lane] = inc - v;
        if (lane == 7) s_n = inc;
    }
    __syncthreads();

    int n_c = s_n;
    if (n_c == 0) {   // out = l2norm(0.98*proto) = proto (unit-norm input)
        #pragma unroll
        for (int j = 0; j < NUM_PROTO; j++)
            out[(size_t)(c * NUM_PROTO + j) * EMBED_D + tid] = sp[j * EMBED_D + tid];
        return;
    }
    bool sm  = (n_c <= NCAP);
    int  off = s_lt;
    int* dst = sm ? sidx : (g_fidx + off);

    // --- pass 2: replay cached masks; thread per sub-chunk, no label reloads ---
    if (tid < 256) {
        unsigned m = cmask[tid];
        if (m) {
            int pos = wsum[tid >> 5] + cpre[tid];
            int k, w, cc;
            if (!is64) { k = tid >> 6; w = (tid >> 2) & 15; cc = tid & 3; }
            else       { k = tid >> 5; w = (tid >> 1) & 15; cc = tid & 1; }
            int mult = is64 ? 2 : 4;
            int base = mult * (32 * w + 512 * k) + cc;
            while (m) {
                int l = __ffs(m) - 1; m &= m - 1;
                dst[pos++] = base + mult * l;
            }
        }
    }
    __syncthreads();

    if (sm) {
        class_body<true >(c, n_c, tokens, out, sp, sidx,
                          ssS, ssV, ssI, su, red, sinv);
    } else {  // statistically unreachable; correct fallback via global scratch
        class_body<false>(c, n_c, tokens, out, sp, g_fidx + off,
                          g_Sf + (size_t)off * NUM_PROTO, g_vf + off, g_if + off,
                          su, red, sinv);
    }
}

// -------------------------------- launch ---------------------------------------
extern "C" void kernel_launch(void* const* d_in, const int* in_sizes, int n_in,
                              void* d_out, int out_size) {
    const float* tokens = (const float*)d_in[0];
    const void*  labels = d_in[1];
    const float* protos = (const float*)d_in[2];
    float* out = (float*)d_out;

    k_main<<<NUM_CLASSES, 512>>>(tokens, labels, protos, out);
}